// round 3
// baseline (speedup 1.0000x reference)
#include <cuda_runtime.h>
#include <float.h>

// Fixed shapes from reference setup_inputs
#define BATCH 4
#define NQ 8192
#define NK 2048
#define CH 128
#define TPB 256
#define GQ 4            // queries per thread
#define SPLIT 8         // threads (key-splits) per query group
#define KEYS_PER_T (NK / SPLIT)            // 256
#define QPB (TPB / SPLIT * GQ)             // 128 queries per block

__device__ __forceinline__ void insert3(float s, int j,
                                        float& d0, float& d1, float& d2,
                                        int& i0, int& i1, int& i2)
{
    if (s < d2) {
        if (s < d1) {
            d2 = d1; i2 = i1;
            if (s < d0) { d1 = d0; i1 = i0; d0 = s; i0 = j; }
            else        { d1 = s;  i1 = j; }
        } else {
            d2 = s; i2 = j;
        }
    }
}

__global__ __launch_bounds__(TPB, 2)
void fp_knn_interp_kernel(const float* __restrict__ xyz_q,
                          const float* __restrict__ xyz_k,
                          const float* __restrict__ v_k,
                          float* __restrict__ out)
{
    __shared__ float4 skey[NK];          // {-2x, -2y, -2z, ||k||^2} -> 32 KB
    __shared__ int    sidx[QPB][3];
    __shared__ float  swgt[QPB][3];

    const int b   = blockIdx.y;
    const int q0  = blockIdx.x * QPB;
    const int tid = threadIdx.x;

    // ---- stage keys (pre-scaled by -2) for this batch into shared memory ----
    const float* kb = xyz_k + (size_t)b * NK * 3;
    for (int j = tid; j < NK; j += TPB) {
        float kx = kb[j * 3 + 0];
        float ky = kb[j * 3 + 1];
        float kz = kb[j * 3 + 2];
        skey[j] = make_float4(-2.0f * kx, -2.0f * ky, -2.0f * kz,
                              fmaf(kx, kx, fmaf(ky, ky, kz * kz)));
    }
    __syncthreads();

    // ---- group structure: 8 threads share 4 queries, each scans 256 keys ----
    const int g  = tid >> 3;        // query group 0..31
    const int L  = tid & 7;         // key-split id 0..7
    const int qb = q0 + g * GQ;     // first query of this group

    float qx[GQ], qy[GQ], qz[GQ], qq[GQ];
    #pragma unroll
    for (int t = 0; t < GQ; ++t) {
        const float* qp = xyz_q + ((size_t)b * NQ + qb + t) * 3;
        qx[t] = qp[0]; qy[t] = qp[1]; qz[t] = qp[2];
        qq[t] = fmaf(qx[t], qx[t], fmaf(qy[t], qy[t], qz[t] * qz[t]));
    }

    // compare on s = ||k||^2 - 2 q.k (same ordering as full sq-dist)
    float d0[GQ], d1[GQ], d2[GQ];
    int   i0[GQ], i1[GQ], i2[GQ];
    #pragma unroll
    for (int t = 0; t < GQ; ++t) {
        d0[t] = FLT_MAX; d1[t] = FLT_MAX; d2[t] = FLT_MAX;
        i0[t] = 0; i1[t] = 0; i2[t] = 0;
    }

    const float4* kbase = skey + L * KEYS_PER_T;
    #pragma unroll 4
    for (int j = 0; j < KEYS_PER_T; ++j) {
        float4 k = kbase[j];                     // 1 LDS.128 serves 4 queries
        #pragma unroll
        for (int t = 0; t < GQ; ++t) {
            float s = fmaf(qx[t], k.x, fmaf(qy[t], k.y, fmaf(qz[t], k.z, k.w)));
            insert3(s, j, d0[t], d1[t], d2[t], i0[t], i1[t], i2[t]);
        }
    }
    const int base = L * KEYS_PER_T;
    #pragma unroll
    for (int t = 0; t < GQ; ++t) { i0[t] += base; i1[t] += base; i2[t] += base; }

    // ---- butterfly merge across the 8 key-splits (xor 1,2,4 within warp) ----
    #pragma unroll
    for (int m = 1; m < SPLIT; m <<= 1) {
        #pragma unroll
        for (int t = 0; t < GQ; ++t) {
            float e0 = __shfl_xor_sync(0xffffffffu, d0[t], m);
            float e1 = __shfl_xor_sync(0xffffffffu, d1[t], m);
            float e2 = __shfl_xor_sync(0xffffffffu, d2[t], m);
            int   j0 = __shfl_xor_sync(0xffffffffu, i0[t], m);
            int   j1 = __shfl_xor_sync(0xffffffffu, i1[t], m);
            int   j2 = __shfl_xor_sync(0xffffffffu, i2[t], m);
            insert3(e0, j0, d0[t], d1[t], d2[t], i0[t], i1[t], i2[t]);
            insert3(e1, j1, d0[t], d1[t], d2[t], i0[t], i1[t], i2[t]);
            insert3(e2, j2, d0[t], d1[t], d2[t], i0[t], i1[t], i2[t]);
        }
    }

    // ---- split leader computes normalized inverse-distance weights ----
    if (L == 0) {
        #pragma unroll
        for (int t = 0; t < GQ; ++t) {
            float w0 = 1.0f / fmaxf(d0[t] + qq[t], 1e-10f);
            float w1 = 1.0f / fmaxf(d1[t] + qq[t], 1e-10f);
            float w2 = 1.0f / fmaxf(d2[t] + qq[t], 1e-10f);
            float inv_sum = 1.0f / (w0 + w1 + w2);
            const int ql = g * GQ + t;
            sidx[ql][0] = i0[t]; sidx[ql][1] = i1[t]; sidx[ql][2] = i2[t];
            swgt[ql][0] = w0 * inv_sum;
            swgt[ql][1] = w1 * inv_sum;
            swgt[ql][2] = w2 * inv_sum;
        }
    }
    __syncthreads();

    // ---- gather epilogue: one warp per query, lane = channel quad ----
    const float4* vb = (const float4*)(v_k + (size_t)b * NK * CH);
    float4* ob = (float4*)(out + ((size_t)b * NQ + q0) * CH);
    const int lane = tid & 31;
    const int warp = tid >> 5;

    #pragma unroll
    for (int ql = warp; ql < QPB; ql += TPB / 32) {
        int   n0 = sidx[ql][0], n1 = sidx[ql][1], n2 = sidx[ql][2];
        float a0 = swgt[ql][0], a1 = swgt[ql][1], a2 = swgt[ql][2];
        float4 va = vb[n0 * (CH / 4) + lane];
        float4 vc = vb[n1 * (CH / 4) + lane];
        float4 vd = vb[n2 * (CH / 4) + lane];
        float4 r;
        r.x = a0 * va.x + a1 * vc.x + a2 * vd.x;
        r.y = a0 * va.y + a1 * vc.y + a2 * vd.y;
        r.z = a0 * va.z + a1 * vc.z + a2 * vd.z;
        r.w = a0 * va.w + a1 * vc.w + a2 * vd.w;
        ob[ql * (CH / 4) + lane] = r;
    }
}

extern "C" void kernel_launch(void* const* d_in, const int* in_sizes, int n_in,
                              void* d_out, int out_size)
{
    const float* xyz_q = (const float*)d_in[0];   // [4, 8192, 3]
    const float* xyz_k = (const float*)d_in[1];   // [4, 2048, 3]
    const float* v_k   = (const float*)d_in[2];   // [4, 2048, 128]
    float* out = (float*)d_out;                   // [4, 8192, 128]

    dim3 grid(NQ / QPB, BATCH);   // (64, 4) = 256 CTAs
    fp_knn_interp_kernel<<<grid, TPB>>>(xyz_q, xyz_k, v_k, out);
}

// round 4
// speedup vs baseline: 1.3488x; 1.3488x over previous
#include <cuda_runtime.h>
#include <float.h>

// Fixed shapes from reference setup_inputs
#define BATCH 4
#define NQ 8192
#define NK 2048
#define CH 128
#define TPB 256
#define GQ 4            // queries per thread
#define SPLIT 8         // threads (key-splits) per query group
#define KEYS_PER_T (NK / SPLIT)            // 256
#define QPB (TPB / SPLIT * GQ)             // 128 queries per block

__device__ __forceinline__ void insert3(float s, int j,
                                        float& d0, float& d1, float& d2,
                                        int& i0, int& i1, int& i2)
{
    if (s < d2) {
        if (s < d1) {
            d2 = d1; i2 = i1;
            if (s < d0) { d1 = d0; i1 = i0; d0 = s; i0 = j; }
            else        { d1 = s;  i1 = j; }
        } else {
            d2 = s; i2 = j;
        }
    }
}

__global__ __launch_bounds__(TPB, 2)
void fp_knn_interp_kernel(const float* __restrict__ xyz_q,
                          const float* __restrict__ xyz_k,
                          const float* __restrict__ v_k,
                          float* __restrict__ out)
{
    __shared__ float4 skey[NK];          // {x, y, z, ||k||^2} -> 32 KB
    __shared__ int    sidx[QPB][3];
    __shared__ float  swgt[QPB][3];

    const int b   = blockIdx.y;
    const int q0  = blockIdx.x * QPB;
    const int tid = threadIdx.x;

    // ---- stage keys for this batch into shared memory ----
    const float* kb = xyz_k + (size_t)b * NK * 3;
    for (int j = tid; j < NK; j += TPB) {
        float kx = kb[j * 3 + 0];
        float ky = kb[j * 3 + 1];
        float kz = kb[j * 3 + 2];
        skey[j] = make_float4(kx, ky, kz,
                              fmaf(kx, kx, fmaf(ky, ky, kz * kz)));
    }
    __syncthreads();

    // ---- group structure: 8 threads share 4 queries ----
    // INTERLEAVED split: thread L scans keys {j*8 + L}. Within a warp,
    // lanes 0..7 hit 8 consecutive 16B chunks (one 128B line) and the
    // other 3 groups broadcast the same addresses -> conflict-free LDS.128.
    const int g  = tid >> 3;        // query group 0..31
    const int L  = tid & 7;         // key-split id 0..7
    const int qb = q0 + g * GQ;     // first query of this group

    float qx[GQ], qy[GQ], qz[GQ], qq[GQ];
    #pragma unroll
    for (int t = 0; t < GQ; ++t) {
        const float* qp = xyz_q + ((size_t)b * NQ + qb + t) * 3;
        qx[t] = -2.0f * qp[0]; qy[t] = -2.0f * qp[1]; qz[t] = -2.0f * qp[2];
        qq[t] = fmaf(qp[0], qp[0], fmaf(qp[1], qp[1], qp[2] * qp[2]));
    }

    // compare on s = ||k||^2 - 2 q.k (same ordering as full sq-dist)
    float d0[GQ], d1[GQ], d2[GQ];
    int   i0[GQ], i1[GQ], i2[GQ];
    #pragma unroll
    for (int t = 0; t < GQ; ++t) {
        d0[t] = FLT_MAX; d1[t] = FLT_MAX; d2[t] = FLT_MAX;
        i0[t] = 0; i1[t] = 0; i2[t] = 0;
    }

    const float4* kbase = skey + L;
    #pragma unroll 4
    for (int j = 0; j < KEYS_PER_T; ++j) {
        float4 k = kbase[j * SPLIT];             // conflict-free LDS.128
        #pragma unroll
        for (int t = 0; t < GQ; ++t) {
            float s = fmaf(qx[t], k.x, fmaf(qy[t], k.y, fmaf(qz[t], k.z, k.w)));
            insert3(s, j, d0[t], d1[t], d2[t], i0[t], i1[t], i2[t]);
        }
    }
    // recover global key index: jj = j*SPLIT + L
    #pragma unroll
    for (int t = 0; t < GQ; ++t) {
        i0[t] = i0[t] * SPLIT + L;
        i1[t] = i1[t] * SPLIT + L;
        i2[t] = i2[t] * SPLIT + L;
    }

    // ---- butterfly merge across the 8 key-splits (xor 1,2,4 within warp) ----
    #pragma unroll
    for (int m = 1; m < SPLIT; m <<= 1) {
        #pragma unroll
        for (int t = 0; t < GQ; ++t) {
            float e0 = __shfl_xor_sync(0xffffffffu, d0[t], m);
            float e1 = __shfl_xor_sync(0xffffffffu, d1[t], m);
            float e2 = __shfl_xor_sync(0xffffffffu, d2[t], m);
            int   j0 = __shfl_xor_sync(0xffffffffu, i0[t], m);
            int   j1 = __shfl_xor_sync(0xffffffffu, i1[t], m);
            int   j2 = __shfl_xor_sync(0xffffffffu, i2[t], m);
            insert3(e0, j0, d0[t], d1[t], d2[t], i0[t], i1[t], i2[t]);
            insert3(e1, j1, d0[t], d1[t], d2[t], i0[t], i1[t], i2[t]);
            insert3(e2, j2, d0[t], d1[t], d2[t], i0[t], i1[t], i2[t]);
        }
    }

    // ---- split leader computes normalized inverse-distance weights ----
    if (L == 0) {
        #pragma unroll
        for (int t = 0; t < GQ; ++t) {
            float w0 = 1.0f / fmaxf(d0[t] + qq[t], 1e-10f);
            float w1 = 1.0f / fmaxf(d1[t] + qq[t], 1e-10f);
            float w2 = 1.0f / fmaxf(d2[t] + qq[t], 1e-10f);
            float inv_sum = 1.0f / (w0 + w1 + w2);
            const int ql = g * GQ + t;
            sidx[ql][0] = i0[t]; sidx[ql][1] = i1[t]; sidx[ql][2] = i2[t];
            swgt[ql][0] = w0 * inv_sum;
            swgt[ql][1] = w1 * inv_sum;
            swgt[ql][2] = w2 * inv_sum;
        }
    }
    __syncthreads();

    // ---- gather epilogue: one warp per query, lane = channel quad ----
    const float4* vb = (const float4*)(v_k + (size_t)b * NK * CH);
    float4* ob = (float4*)(out + ((size_t)b * NQ + q0) * CH);
    const int lane = tid & 31;
    const int warp = tid >> 5;

    #pragma unroll
    for (int ql = warp; ql < QPB; ql += TPB / 32) {
        int   n0 = sidx[ql][0], n1 = sidx[ql][1], n2 = sidx[ql][2];
        float a0 = swgt[ql][0], a1 = swgt[ql][1], a2 = swgt[ql][2];
        float4 va = vb[n0 * (CH / 4) + lane];
        float4 vc = vb[n1 * (CH / 4) + lane];
        float4 vd = vb[n2 * (CH / 4) + lane];
        float4 r;
        r.x = a0 * va.x + a1 * vc.x + a2 * vd.x;
        r.y = a0 * va.y + a1 * vc.y + a2 * vd.y;
        r.z = a0 * va.z + a1 * vc.z + a2 * vd.z;
        r.w = a0 * va.w + a1 * vc.w + a2 * vd.w;
        ob[ql * (CH / 4) + lane] = r;
    }
}

extern "C" void kernel_launch(void* const* d_in, const int* in_sizes, int n_in,
                              void* d_out, int out_size)
{
    const float* xyz_q = (const float*)d_in[0];   // [4, 8192, 3]
    const float* xyz_k = (const float*)d_in[1];   // [4, 2048, 3]
    const float* v_k   = (const float*)d_in[2];   // [4, 2048, 128]
    float* out = (float*)d_out;                   // [4, 8192, 128]

    dim3 grid(NQ / QPB, BATCH);   // (64, 4) = 256 CTAs
    fp_knn_interp_kernel<<<grid, TPB>>>(xyz_q, xyz_k, v_k, out);
}